// round 14
// baseline (speedup 1.0000x reference)
#include <cuda_runtime.h>
#include <stdint.h>

#define NDU 60000
#define NDI 90000
#define NDOM (NDU + NDI)      /* 150000 */
#define NTU 200000
#define NTI 300000
#define NALL (NTU + NTI)      /* 500000 */
#define NE  2000000
#define DIM 32
#define NQ  8192
#define ALPHA 0.1f
#define BETA  0.9f
#define CPAD 256
#define NBITW ((4 * NALL) / 32)   /* 62500 */
#define NBL   4704
#define NBG   15628
#define DBLK 512
#define QNE  500000               /* NE/4: threads per set in degA */

/* ---------------- static device scratch (no allocs allowed) ---------------- */
__device__ __align__(16) float g_A[(size_t)4 * NALL * DIM];
__device__ __align__(16) float g_res[(size_t)2 * NDOM * DIM]; /* intra | light */
__device__ __align__(16) float    g_deg[4 * (size_t)NALL];
__device__ __align__(16) float2   g_pack[4 * (size_t)NALL];  /* (nrm, denseRow) */
__device__ __align__(16) int      g_l2s[4 * (size_t)NE];
__device__ __align__(16) int      g_l2d[4 * (size_t)NE];
__device__ __align__(16) int      g_l2r[4 * (size_t)NE];
__device__ __align__(16) int      g_ini[4 * (size_t)NALL];
__device__ __align__(16) unsigned g_needA[NBITW];
__device__ __align__(16) unsigned g_bitL[NBL];
__device__ __align__(16) unsigned g_bitG[NBG];
__device__ __align__(16) int      g_remap[NALL];
__device__ int      g_cnt[3 * CPAD];
__device__ int      g_f[2] = {1, 1};

/* ---------------- edge-list addressing ---------------- */
__device__ __forceinline__ const int* src_ptr(int set, const int* dom, const int* sep) {
    return (set == 0) ? dom : sep + (size_t)(set - 1) * 2 * NE;
}
__device__ __forceinline__ const int* dst_ptr(int set, const int* dom, const int* sep) {
    return (set == 0) ? dom + NE : sep + (size_t)(set - 1) * 2 * NE + NE;
}

__device__ __forceinline__ float nrm(float deg) { return rsqrtf(fmaxf(deg, 1.0f)); }
__device__ __forceinline__ bool bit_test(const unsigned* __restrict__ b, int i) {
    return (__ldg(b + (i >> 5)) >> (i & 31)) & 1u;
}
__device__ __forceinline__ long long qidx(const void* p, int flag, int i) {
    return flag ? ((const long long*)p)[i] : (long long)((const int*)p)[i];
}

/* ---------------- setup: clear + width-detect fused ---------------- */
__global__ void k_cleardet(float4* __restrict__ deg4, uint4* __restrict__ needA4,
                           uint4* __restrict__ bitL4, uint4* __restrict__ bitG4,
                           int* __restrict__ cnt,
                           const int* __restrict__ ua, const int* __restrict__ ib) {
    int i = blockIdx.x * blockDim.x + threadIdx.x;
    if (i < 500000) deg4[i] = make_float4(0.f, 0.f, 0.f, 0.f);
    if (i < 15625)  needA4[i] = make_uint4(0u, 0u, 0u, 0u);
    if (i < NBL / 4) bitL4[i] = make_uint4(0u, 0u, 0u, 0u);
    if (i < NBG / 4) bitG4[i] = make_uint4(0u, 0u, 0u, 0u);
    if (i < 3 * CPAD) cnt[i] = 0;
    /* monotone width detect: only ever writes 0; int32 re-flips every call */
    if (i < NQ) {
        if (ua[2 * i + 1] != 0) g_f[0] = 0;
        if (ib[2 * i + 1] != 0) g_f[1] = 0;
    }
}
__global__ void k_needmap(unsigned* __restrict__ bitL, unsigned* __restrict__ bitG,
                          int* __restrict__ remap,
                          const int* __restrict__ uid, const int* __restrict__ iid,
                          const void* __restrict__ users, const void* __restrict__ items) {
    int i = blockIdx.x * blockDim.x + threadIdx.x;
    if (i >= NQ) return;
    long long u  = qidx(users, g_f[0], i);
    long long it = qidx(items, g_f[1], i);
    int r1 = (int)u, r2 = NDU + (int)it;
    atomicOr(&bitL[r1 >> 5], 1u << (r1 & 31));
    atomicOr(&bitL[r2 >> 5], 1u << (r2 & 31));
    int n1 = __ldg(uid + u), n2 = NTU + __ldg(iid + it);
    atomicOr(&bitG[n1 >> 5], 1u << (n1 & 31));
    atomicOr(&bitG[n2 >> 5], 1u << (n2 & 31));
    remap[n1] = r1;
    remap[n2] = r2;
}

/* ---------------- degA: 4 edges/thread; deg histogram + L2 compaction +
   needA marking. One counter atomic per block.                            */
__global__ __launch_bounds__(DBLK) void
k_degA(const int* __restrict__ dom, const int* __restrict__ sep,
       float* __restrict__ deg, const unsigned* __restrict__ bitL,
       const unsigned* __restrict__ bitG, const int* __restrict__ remap,
       unsigned* __restrict__ needA, int* __restrict__ cnt,
       int* __restrict__ l2s, int* __restrict__ l2d, int* __restrict__ l2r) {
    __shared__ int w2[DBLK / 32];
    __shared__ int base2;
    size_t t = (size_t)blockIdx.x * DBLK + threadIdx.x;
    bool in = t < (size_t)4 * QNE;
    size_t tt = in ? t : 0;
    int lane = threadIdx.x & 31, wid = threadIdx.x >> 5;
    int set = (int)(tt / QNE);
    int e   = (int)(tt - (size_t)set * QNE) * 4;
    const int* dp = dst_ptr(set, dom, sep);
    int4 dd = __ldg((const int4*)(dp + e));
    float* dg = deg + (size_t)set * NALL;
    if (in) {
        atomicAdd(dg + dd.x, 1.0f);
        atomicAdd(dg + dd.y, 1.0f);
        atomicAdd(dg + dd.z, 1.0f);
        atomicAdd(dg + dd.w, 1.0f);
    }
    bool vA = false, vB = false, vC = false, vD = false;
    int rA = 0, rB = 0, rC = 0, rD = 0;
    if (in) {
        if (set == 0) {
            vA = bit_test(bitL, dd.x); rA = dd.x;
            vB = bit_test(bitL, dd.y); rB = dd.y;
            vC = bit_test(bitL, dd.z); rC = dd.z;
            vD = bit_test(bitL, dd.w); rD = dd.w;
        } else {
            vA = bit_test(bitG, dd.x);
            vB = bit_test(bitG, dd.y);
            vC = bit_test(bitG, dd.z);
            vD = bit_test(bitG, dd.w);
            if (vA) rA = NDOM + __ldg(remap + dd.x);
            if (vB) rB = NDOM + __ldg(remap + dd.y);
            if (vC) rC = NDOM + __ldg(remap + dd.z);
            if (vD) rD = NDOM + __ldg(remap + dd.w);
        }
    }
    int iA = 0, iB = 0, iC = 0, iD = 0;
    if (vA | vB | vC | vD) {
        const int* sp = src_ptr(set, dom, sep);
        int4 ss = __ldg((const int4*)(sp + e));
        iA = set * NALL + ss.x; iB = set * NALL + ss.y;
        iC = set * NALL + ss.z; iD = set * NALL + ss.w;
        if (vA) atomicOr(&needA[iA >> 5], 1u << (iA & 31));
        if (vB) atomicOr(&needA[iB >> 5], 1u << (iB & 31));
        if (vC) atomicOr(&needA[iC >> 5], 1u << (iC & 31));
        if (vD) atomicOr(&needA[iD >> 5], 1u << (iD & 31));
    }
    unsigned mA = __ballot_sync(0xffffffffu, vA);
    unsigned mB = __ballot_sync(0xffffffffu, vB);
    unsigned mC = __ballot_sync(0xffffffffu, vC);
    unsigned mD = __ballot_sync(0xffffffffu, vD);
    if (lane == 0) w2[wid] = __popc(mA) + __popc(mB) + __popc(mC) + __popc(mD);
    __syncthreads();
    if (threadIdx.x == 0) {
        int tot = 0;
#pragma unroll
        for (int i = 0; i < DBLK / 32; i++) { int c = w2[i]; w2[i] = tot; tot += c; }
        base2 = tot ? atomicAdd(&cnt[0], tot) : 0;
    }
    __syncthreads();
    unsigned ltm = (1u << lane) - 1u;
    int wb = base2 + w2[wid];
    int cA = __popc(mA), cB = __popc(mB), cC = __popc(mC);
    if (vA) { int p = wb + __popc(mA & ltm);                 l2s[p] = iA; l2d[p] = dd.x; l2r[p] = rA; }
    if (vB) { int p = wb + cA + __popc(mB & ltm);            l2s[p] = iB; l2d[p] = dd.y; l2r[p] = rB; }
    if (vC) { int p = wb + cA + cB + __popc(mC & ltm);       l2s[p] = iC; l2d[p] = dd.z; l2r[p] = rC; }
    if (vD) { int p = wb + cA + cB + cC + __popc(mD & ltm);  l2s[p] = iD; l2d[p] = dd.w; l2r[p] = rD; }
}

/* ---------------- build ini list + pack from needA bitmask ---------------- */
__global__ void k_build(const unsigned* __restrict__ needA, const float* __restrict__ deg,
                        int* __restrict__ ini, float2* __restrict__ pack,
                        int* __restrict__ cnt) {
    __shared__ int wtot[8];
    __shared__ int sBase;
    int w = blockIdx.x * 256 + threadIdx.x;
    int lane = threadIdx.x & 31, wid = threadIdx.x >> 5;
    unsigned word = (w < NBITW) ? needA[w] : 0u;
    int c = __popc(word);
    int x = c;
#pragma unroll
    for (int off = 1; off < 32; off <<= 1) {
        int y = __shfl_up_sync(0xffffffffu, x, off);
        if (lane >= off) x += y;
    }
    if (lane == 31) wtot[wid] = x;
    __syncthreads();
    if (threadIdx.x == 0) {
        int tot = 0;
#pragma unroll
        for (int i = 0; i < 8; i++) { int t = wtot[i]; wtot[i] = tot; tot += t; }
        sBase = tot ? atomicAdd(&cnt[2 * CPAD], tot) : 0;
    }
    __syncthreads();
    int off0 = sBase + wtot[wid] + (x - c);
    int k = 0;
    while (word) {
        int b = __ffs(word) - 1;
        word &= word - 1;
        int node = w * 32 + b;
        int r = off0 + k++;
        ini[r] = node;
        pack[node] = make_float2(nrm(__ldg(deg + node)), __int_as_float(r));
    }
}

/* ---------------- gathers from split input tables ---------------- */
__device__ __forceinline__ float4 gatherX(const float* __restrict__ xu,
                                          const float* __restrict__ xi,
                                          int splitU, int node, int lane) {
    const float* p = (node < splitU) ? xu + (size_t)node * DIM
                                     : xi + (size_t)(node - splitU) * DIM;
    return *(const float4*)(p + lane * 4);
}

/* ---------------- inits: query-driven res rows + dense A rows ------------- */
__global__ void k_inits(const int* __restrict__ ini, const int* __restrict__ cnt,
                        const float* __restrict__ du, const float* __restrict__ di,
                        const float* __restrict__ au, const float* __restrict__ ai,
                        const int* __restrict__ uid, const int* __restrict__ iid,
                        const void* __restrict__ users, const void* __restrict__ items,
                        float* __restrict__ A, float* __restrict__ res) {
    const size_t seg = (size_t)NQ * 8;
    const size_t fixed = 4 * seg;
    size_t work = fixed + (size_t)__ldg(&cnt[2 * CPAD]) * 8;
    size_t stride = (size_t)gridDim.x * blockDim.x;
    int f0 = g_f[0], f1 = g_f[1];
    for (size_t i = (size_t)blockIdx.x * blockDim.x + threadIdx.x; i < work; i += stride) {
        if (i < fixed) {
            int sg = (int)(i / seg);
            int j  = (int)(i - (size_t)sg * seg);
            int q = j >> 3, c = j & 7;
            size_t row;
            float4 v;
            float k;
            if (sg == 0) {        /* intra user */
                long long u = qidx(users, f0, q);
                row = (size_t)u;
                v = *(const float4*)(du + u * DIM + c * 4);
                k = ALPHA;
            } else if (sg == 1) { /* intra item */
                long long it = qidx(items, f1, q);
                row = (size_t)NDU + it;
                v = *(const float4*)(di + it * DIM + c * 4);
                k = ALPHA;
            } else if (sg == 2) { /* light user */
                long long u = qidx(users, f0, q);
                row = (size_t)NDOM + u;
                v = *(const float4*)(au + (size_t)__ldg(uid + u) * DIM + c * 4);
                k = 3.0f * ALPHA;
            } else {              /* light item */
                long long it = qidx(items, f1, q);
                row = (size_t)NDOM + NDU + it;
                v = *(const float4*)(ai + (size_t)__ldg(iid + it) * DIM + c * 4);
                k = 3.0f * ALPHA;
            }
            *(float4*)(res + row * DIM + c * 4) =
                make_float4(k * v.x, k * v.y, k * v.z, k * v.w);
        } else {
            size_t j = i - fixed;
            int r = (int)(j >> 3), lane = (int)(j & 7);
            int node = __ldg(ini + r);
            int set = node / NALL;
            int so = node - set * NALL;
            float4 v = (set == 0) ? gatherX(du, di, NDU, so, lane)
                                  : gatherX(au, ai, NTU, so, lane);
            *(float4*)(A + (size_t)r * DIM + lane * 4) =
                make_float4(ALPHA * v.x, ALPHA * v.y, ALPHA * v.z, ALPHA * v.w);
        }
    }
}

/* ---------------- fused layer-1: 4 edges/lane filter + warp-compacted scatter */
__device__ __forceinline__ void l1_process(unsigned m, int scode, int drow, float w,
                                           unsigned lane,
                                           const float* __restrict__ du,
                                           const float* __restrict__ di,
                                           const float* __restrict__ au,
                                           const float* __restrict__ ai,
                                           float* __restrict__ A) {
    int nv = __popc(m);
    for (int k = 0; k < nv; k += 4) {
        int j = k + (int)(lane >> 3);
        unsigned sl = __fns(m, 0, j + 1);
        int   sc = __shfl_sync(0xffffffffu, scode, sl & 31);
        int   dr = __shfl_sync(0xffffffffu, drow,  sl & 31);
        float ww = __shfl_sync(0xffffffffu, w,     sl & 31);
        if (j < nv) {
            int so = sc & 0x3FFFFFFF;
            int sub = (int)(lane & 7);
            float4 v = (sc >> 30) ? gatherX(au, ai, NTU, so, sub)
                                  : gatherX(du, di, NDU, so, sub);
            float* o = A + (size_t)dr * DIM + sub * 4;
            asm volatile("red.global.add.v4.f32 [%0], {%1,%2,%3,%4};"
                         :: "l"(o), "f"(v.x * ww), "f"(v.y * ww),
                            "f"(v.z * ww), "f"(v.w * ww) : "memory");
        }
    }
}
__global__ void k_scatL1f(const int* __restrict__ dom, const int* __restrict__ sep,
                          const float* __restrict__ deg, const unsigned* __restrict__ needA,
                          const float2* __restrict__ pack,
                          const float* __restrict__ du, const float* __restrict__ di,
                          const float* __restrict__ au, const float* __restrict__ ai,
                          float* __restrict__ A) {
    const unsigned total = 4u * NE;
    unsigned lane = threadIdx.x & 31;
    unsigned warpStride = (gridDim.x * blockDim.x) >> 5;
    unsigned warpId = ((blockIdx.x * blockDim.x) >> 5) + (threadIdx.x >> 5);
    for (unsigned base = warpId * 128; base < total; base += warpStride * 128) {
        unsigned t = base + lane * 4;
        int set = (int)(t / NE);                 /* uniform: NE%128==0 */
        int e   = (int)(t - (unsigned)set * NE);
        const int* dp = dst_ptr(set, dom, sep);
        int4 dd = __ldg((const int4*)(dp + e));
        int iA = set * NALL + dd.x, iB = set * NALL + dd.y;
        int iC = set * NALL + dd.z, iD = set * NALL + dd.w;
        bool vA = bit_test(needA, iA), vB = bit_test(needA, iB);
        bool vC = bit_test(needA, iC), vD = bit_test(needA, iD);
        float wA = 0.f, wB = 0.f, wC = 0.f, wD = 0.f;
        int drA = 0, drB = 0, drC = 0, drD = 0;
        int scA = 0, scB = 0, scC = 0, scD = 0;
        if (vA | vB | vC | vD) {
            const int* sp = src_ptr(set, dom, sep);
            int4 ss = __ldg((const int4*)(sp + e));
            const float* dg = deg + (size_t)set * NALL;
            int tb = (set > 0) << 30;
            if (vA) { float2 pk = __ldg(pack + iA);
                      wA = BETA * nrm(__ldg(dg + ss.x)) * pk.x;
                      drA = __float_as_int(pk.y); scA = ss.x | tb; }
            if (vB) { float2 pk = __ldg(pack + iB);
                      wB = BETA * nrm(__ldg(dg + ss.y)) * pk.x;
                      drB = __float_as_int(pk.y); scB = ss.y | tb; }
            if (vC) { float2 pk = __ldg(pack + iC);
                      wC = BETA * nrm(__ldg(dg + ss.z)) * pk.x;
                      drC = __float_as_int(pk.y); scC = ss.z | tb; }
            if (vD) { float2 pk = __ldg(pack + iD);
                      wD = BETA * nrm(__ldg(dg + ss.w)) * pk.x;
                      drD = __float_as_int(pk.y); scD = ss.w | tb; }
        }
        unsigned mA = __ballot_sync(0xffffffffu, vA);
        unsigned mB = __ballot_sync(0xffffffffu, vB);
        unsigned mC = __ballot_sync(0xffffffffu, vC);
        unsigned mD = __ballot_sync(0xffffffffu, vD);
        if (mA) l1_process(mA, scA, drA, wA, lane, du, di, au, ai, A);
        if (mB) l1_process(mB, scB, drB, wB, lane, du, di, au, ai, A);
        if (mC) l1_process(mC, scC, drC, wC, lane, du, di, au, ai, A);
        if (mD) l1_process(mD, scD, drD, wD, lane, du, di, au, ai, A);
    }
}

/* ---------------- layer-2 scatter with fused resolve: 4 edges per warp ---- */
__global__ void k_scatL2(const int* __restrict__ l2s, const int* __restrict__ l2d,
                         const int* __restrict__ l2r, const int* __restrict__ cnt,
                         const float* __restrict__ deg, const float2* __restrict__ pack,
                         const float* __restrict__ A, float* __restrict__ res) {
    int n = __ldg(&cnt[0]);
    unsigned lane = threadIdx.x & 31;
    unsigned warpStride = (gridDim.x * blockDim.x) >> 5;
    unsigned warpId = ((blockIdx.x * blockDim.x) >> 5) + (threadIdx.x >> 5);
    int j = (int)(lane >> 3), sub = (int)(lane & 7);
    for (int eb = (int)warpId * 4; eb < n; eb += (int)warpStride * 4) {
        int e = eb + j;
        float w = 0.f;
        int drow = 0, rrow = 0;
        if (sub == 0 && e < n) {
            int srow = __ldg(l2s + e);
            int set = srow / NALL;
            float2 pk = __ldg(pack + srow);
            w = BETA * pk.x * nrm(__ldg(deg + (size_t)set * NALL + __ldg(l2d + e)));
            drow = __float_as_int(pk.y);
            rrow = __ldg(l2r + e);
        }
        unsigned lead = lane & ~7u;
        w    = __shfl_sync(0xffffffffu, w,    lead);
        drow = __shfl_sync(0xffffffffu, drow, lead);
        rrow = __shfl_sync(0xffffffffu, rrow, lead);
        if (e < n) {
            float4 v = *(const float4*)(A + (size_t)drow * DIM + sub * 4);
            float* o = res + (size_t)rrow * DIM + sub * 4;
            asm volatile("red.global.add.v4.f32 [%0], {%1,%2,%3,%4};"
                         :: "l"(o), "f"(v.x * w), "f"(v.y * w),
                            "f"(v.z * w), "f"(v.w * w) : "memory");
        }
    }
}

/* gamma[p] = dot(light_u, light_i)/9 + dot(intra_u, intra_i); one warp/pair */
__global__ void k_gamma(const void* __restrict__ users, const void* __restrict__ items,
                        const float* __restrict__ res, float* __restrict__ out) {
    int p = (blockIdx.x * blockDim.x + threadIdx.x) >> 5;
    int lane = threadIdx.x & 31;
    if (p >= NQ) return;
    long long u  = qidx(users, g_f[0], p);
    long long it = qidx(items, g_f[1], p);
    size_t ui = (size_t)u * DIM + lane;
    size_t ii = ((size_t)NDU + it) * DIM + lane;
    size_t ul = ((size_t)NDOM + u) * DIM + lane;
    size_t il = ((size_t)NDOM + NDU + it) * DIM + lane;
    float v = res[ul] * res[il] * (1.0f / 9.0f) + res[ui] * res[ii];
#pragma unroll
    for (int o = 16; o; o >>= 1) v += __shfl_xor_sync(0xffffffffu, v, o);
    if (lane == 0) out[p] = v;
}

/* ---------------- host side ---------------- */
static inline unsigned gb(size_t n) { return (unsigned)((n + 255) / 256); }

extern "C" void kernel_launch(void* const* d_in, const int* in_sizes, int n_in,
                              void* d_out, int out_size) {
    const int*   dom   = (const int*)d_in[0];
    const int*   sep   = (const int*)d_in[1];
    const float* aggru = (const float*)d_in[2];
    const float* aggri = (const float*)d_in[3];
    const float* domu  = (const float*)d_in[4];
    const float* domi  = (const float*)d_in[5];
    const int*   uid   = (const int*)d_in[6];
    const int*   iid   = (const int*)d_in[7];
    const void*  users = d_in[8];
    const void*  items = d_in[9];
    float* out = (float*)d_out;

    float *A, *res, *deg;
    float2* pack;
    int *l2s, *l2d, *l2r, *ini, *remap, *cnt;
    unsigned *needA, *bitL, *bitG;
    cudaGetSymbolAddress((void**)&A, g_A);
    cudaGetSymbolAddress((void**)&res, g_res);
    cudaGetSymbolAddress((void**)&deg, g_deg);
    cudaGetSymbolAddress((void**)&pack, g_pack);
    cudaGetSymbolAddress((void**)&l2s, g_l2s);
    cudaGetSymbolAddress((void**)&l2d, g_l2d);
    cudaGetSymbolAddress((void**)&l2r, g_l2r);
    cudaGetSymbolAddress((void**)&ini, g_ini);
    cudaGetSymbolAddress((void**)&needA, g_needA);
    cudaGetSymbolAddress((void**)&bitL, g_bitL);
    cudaGetSymbolAddress((void**)&bitG, g_bitG);
    cudaGetSymbolAddress((void**)&remap, g_remap);
    cudaGetSymbolAddress((void**)&cnt, g_cnt);

    /* setup (clear + detect fused) */
    k_cleardet<<<gb(500000), 256>>>((float4*)deg, (uint4*)needA,
                                    (uint4*)bitL, (uint4*)bitG, cnt,
                                    (const int*)users, (const int*)items);
    k_needmap<<<gb(NQ), 256>>>(bitL, bitG, remap, uid, iid, users, items);

    /* degree + layer-2 compaction, then needA -> ini/pack */
    unsigned degGrid = (unsigned)(((size_t)4 * QNE + DBLK - 1) / DBLK);
    k_degA<<<degGrid, DBLK>>>(dom, sep, deg, bitL, bitG, remap, needA, cnt,
                              l2s, l2d, l2r);
    k_build<<<(NBITW + 255) / 256, 256>>>(needA, deg, ini, pack, cnt);

    /* query-driven inits + layer-1 fused scatter */
    k_inits<<<2048, 256>>>(ini, cnt, domu, domi, aggru, aggri, uid, iid,
                           users, items, A, res);
    k_scatL1f<<<2048, 256>>>(dom, sep, deg, needA, pack,
                             domu, domi, aggru, aggri, A);

    /* layer-2 scatter (resolve fused) */
    k_scatL2<<<1024, 256>>>(l2s, l2d, l2r, cnt, deg, pack, A, res);

    /* final dots */
    k_gamma<<<NQ / 8, 256>>>(users, items, res, out);
}

// round 15
// speedup vs baseline: 1.1001x; 1.1001x over previous
#include <cuda_runtime.h>
#include <stdint.h>

#define NDU 60000
#define NDI 90000
#define NDOM (NDU + NDI)      /* 150000 */
#define NTU 200000
#define NTI 300000
#define NALL (NTU + NTI)      /* 500000 */
#define NE  2000000
#define DIM 32
#define NQ  8192
#define ALPHA 0.1f
#define BETA  0.9f
#define CPAD 256
#define NBITW ((4 * NALL) / 32)   /* 62500 */
#define NBL   4704
#define NBG   15628
#define DBLK 512
#define QNE  500000               /* NE/4: threads per set in degA */

/* ---------------- static device scratch (no allocs allowed) ---------------- */
__device__ __align__(16) float g_A[(size_t)4 * NALL * DIM];
__device__ __align__(16) float g_res[(size_t)2 * NDOM * DIM]; /* intra | light */
__device__ __align__(16) float    g_deg[4 * (size_t)NALL];
__device__ __align__(16) float2   g_pack[4 * (size_t)NALL];  /* (nrm, denseRow) */
__device__ __align__(16) int      g_l2s[4 * (size_t)NE];
__device__ __align__(16) int      g_l2d[4 * (size_t)NE];
__device__ __align__(16) int      g_l2r[4 * (size_t)NE];
__device__ __align__(16) int      g_ini[4 * (size_t)NALL];
__device__ __align__(16) unsigned g_needA[NBITW];
__device__ __align__(16) unsigned g_bitL[NBL];
__device__ __align__(16) unsigned g_bitG[NBG];
__device__ __align__(16) int      g_remap[NALL];
__device__ int      g_cnt[3 * CPAD];
__device__ int      g_f[2] = {1, 1};

/* ---------------- edge-list addressing ---------------- */
__device__ __forceinline__ const int* src_ptr(int set, const int* dom, const int* sep) {
    return (set == 0) ? dom : sep + (size_t)(set - 1) * 2 * NE;
}
__device__ __forceinline__ const int* dst_ptr(int set, const int* dom, const int* sep) {
    return (set == 0) ? dom + NE : sep + (size_t)(set - 1) * 2 * NE + NE;
}

__device__ __forceinline__ float nrm(float deg) { return rsqrtf(fmaxf(deg, 1.0f)); }
__device__ __forceinline__ bool bit_test(const unsigned* __restrict__ b, int i) {
    return (__ldg(b + (i >> 5)) >> (i & 31)) & 1u;
}

/* ---------------- setup ---------------- */
__global__ void k_detect(const int* __restrict__ a, const int* __restrict__ b) {
    int arr = blockIdx.x >> 5;
    const int* p = arr ? b : a;
    int i = (blockIdx.x & 31) * 256 + threadIdx.x;
    if (i < NQ && p[2 * i + 1] != 0) g_f[arr] = 0;
}
__global__ void k_clear(float4* __restrict__ deg4, uint4* __restrict__ needA4,
                        uint4* __restrict__ bitL4, uint4* __restrict__ bitG4,
                        int* __restrict__ cnt) {
    int i = blockIdx.x * blockDim.x + threadIdx.x;
    if (i < 500000) deg4[i] = make_float4(0.f, 0.f, 0.f, 0.f);
    if (i < 15625)  needA4[i] = make_uint4(0u, 0u, 0u, 0u);
    if (i < NBL / 4) bitL4[i] = make_uint4(0u, 0u, 0u, 0u);
    if (i < NBG / 4) bitG4[i] = make_uint4(0u, 0u, 0u, 0u);
    if (i < 3 * CPAD) cnt[i] = 0;
}
__global__ void k_needmap(unsigned* __restrict__ bitL, unsigned* __restrict__ bitG,
                          int* __restrict__ remap,
                          const int* __restrict__ uid, const int* __restrict__ iid,
                          const void* __restrict__ users, const void* __restrict__ items) {
    int i = blockIdx.x * blockDim.x + threadIdx.x;
    if (i >= NQ) return;
    long long u  = g_f[0] ? ((const long long*)users)[i] : (long long)((const int*)users)[i];
    long long it = g_f[1] ? ((const long long*)items)[i] : (long long)((const int*)items)[i];
    int r1 = (int)u, r2 = NDU + (int)it;
    atomicOr(&bitL[r1 >> 5], 1u << (r1 & 31));
    atomicOr(&bitL[r2 >> 5], 1u << (r2 & 31));
    int n1 = __ldg(uid + u), n2 = NTU + __ldg(iid + it);
    atomicOr(&bitG[n1 >> 5], 1u << (n1 & 31));
    atomicOr(&bitG[n2 >> 5], 1u << (n2 & 31));
    remap[n1] = r1;
    remap[n2] = r2;
}

/* ---------------- degA: 4 edges/thread (int4); deg histogram + L2 compaction
   + needA marking. One counter atomic per block.                            */
__global__ __launch_bounds__(DBLK) void
k_degA(const int* __restrict__ dom, const int* __restrict__ sep,
       float* __restrict__ deg, const unsigned* __restrict__ bitL,
       const unsigned* __restrict__ bitG, const int* __restrict__ remap,
       unsigned* __restrict__ needA, int* __restrict__ cnt,
       int* __restrict__ l2s, int* __restrict__ l2d, int* __restrict__ l2r) {
    __shared__ int w2[DBLK / 32];
    __shared__ int base2;
    size_t t = (size_t)blockIdx.x * DBLK + threadIdx.x;
    bool in = t < (size_t)4 * QNE;
    size_t tt = in ? t : 0;
    int lane = threadIdx.x & 31, wid = threadIdx.x >> 5;
    int set = (int)(tt / QNE);                  /* uniform per warp: QNE%32==0 */
    int e   = (int)(tt - (size_t)set * QNE) * 4;
    const int* dp = dst_ptr(set, dom, sep);
    int4 dd = __ldg((const int4*)(dp + e));
    float* dg = deg + (size_t)set * NALL;
    if (in) {
        atomicAdd(dg + dd.x, 1.0f);
        atomicAdd(dg + dd.y, 1.0f);
        atomicAdd(dg + dd.z, 1.0f);
        atomicAdd(dg + dd.w, 1.0f);
    }
    bool vA = false, vB = false, vC = false, vD = false;
    int rA = 0, rB = 0, rC = 0, rD = 0;
    if (in) {
        if (set == 0) {
            vA = bit_test(bitL, dd.x); rA = dd.x;
            vB = bit_test(bitL, dd.y); rB = dd.y;
            vC = bit_test(bitL, dd.z); rC = dd.z;
            vD = bit_test(bitL, dd.w); rD = dd.w;
        } else {
            vA = bit_test(bitG, dd.x);
            vB = bit_test(bitG, dd.y);
            vC = bit_test(bitG, dd.z);
            vD = bit_test(bitG, dd.w);
            if (vA) rA = NDOM + __ldg(remap + dd.x);
            if (vB) rB = NDOM + __ldg(remap + dd.y);
            if (vC) rC = NDOM + __ldg(remap + dd.z);
            if (vD) rD = NDOM + __ldg(remap + dd.w);
        }
    }
    int iA = 0, iB = 0, iC = 0, iD = 0;
    if (vA | vB | vC | vD) {
        const int* sp = src_ptr(set, dom, sep);
        int4 ss = __ldg((const int4*)(sp + e));
        iA = set * NALL + ss.x; iB = set * NALL + ss.y;
        iC = set * NALL + ss.z; iD = set * NALL + ss.w;
        if (vA) atomicOr(&needA[iA >> 5], 1u << (iA & 31));
        if (vB) atomicOr(&needA[iB >> 5], 1u << (iB & 31));
        if (vC) atomicOr(&needA[iC >> 5], 1u << (iC & 31));
        if (vD) atomicOr(&needA[iD >> 5], 1u << (iD & 31));
    }
    unsigned mA = __ballot_sync(0xffffffffu, vA);
    unsigned mB = __ballot_sync(0xffffffffu, vB);
    unsigned mC = __ballot_sync(0xffffffffu, vC);
    unsigned mD = __ballot_sync(0xffffffffu, vD);
    if (lane == 0) w2[wid] = __popc(mA) + __popc(mB) + __popc(mC) + __popc(mD);
    __syncthreads();
    if (threadIdx.x == 0) {
        int tot = 0;
#pragma unroll
        for (int i = 0; i < DBLK / 32; i++) { int c = w2[i]; w2[i] = tot; tot += c; }
        base2 = tot ? atomicAdd(&cnt[0], tot) : 0;
    }
    __syncthreads();
    unsigned ltm = (1u << lane) - 1u;
    int wb = base2 + w2[wid];
    int cA = __popc(mA), cB = __popc(mB), cC = __popc(mC);
    if (vA) { int p = wb + __popc(mA & ltm);                 l2s[p] = iA; l2d[p] = dd.x; l2r[p] = rA; }
    if (vB) { int p = wb + cA + __popc(mB & ltm);            l2s[p] = iB; l2d[p] = dd.y; l2r[p] = rB; }
    if (vC) { int p = wb + cA + cB + __popc(mC & ltm);       l2s[p] = iC; l2d[p] = dd.z; l2r[p] = rC; }
    if (vD) { int p = wb + cA + cB + cC + __popc(mD & ltm);  l2s[p] = iD; l2d[p] = dd.w; l2r[p] = rD; }
}

/* ---------------- build ini list from needA bitmask (pure bit-scan) ------- */
__global__ void k_build(const unsigned* __restrict__ needA,
                        int* __restrict__ ini, int* __restrict__ cnt) {
    __shared__ int wtot[8];
    __shared__ int sBase;
    int w = blockIdx.x * 256 + threadIdx.x;
    int lane = threadIdx.x & 31, wid = threadIdx.x >> 5;
    unsigned word = (w < NBITW) ? needA[w] : 0u;
    int c = __popc(word);
    int x = c;
#pragma unroll
    for (int off = 1; off < 32; off <<= 1) {
        int y = __shfl_up_sync(0xffffffffu, x, off);
        if (lane >= off) x += y;
    }
    if (lane == 31) wtot[wid] = x;
    __syncthreads();
    if (threadIdx.x == 0) {
        int tot = 0;
#pragma unroll
        for (int i = 0; i < 8; i++) { int t = wtot[i]; wtot[i] = tot; tot += t; }
        sBase = tot ? atomicAdd(&cnt[2 * CPAD], tot) : 0;
    }
    __syncthreads();
    int off0 = sBase + wtot[wid] + (x - c);
    int k = 0;
    while (word) {
        int b = __ffs(word) - 1;
        word &= word - 1;
        ini[off0 + k++] = w * 32 + b;
    }
}

/* ---------------- gathers from split input tables ---------------- */
__device__ __forceinline__ float4 gatherX(const float* __restrict__ xu,
                                          const float* __restrict__ xi,
                                          int splitU, int node, int lane) {
    const float* p = (node < splitU) ? xu + (size_t)node * DIM
                                     : xi + (size_t)(node - splitU) * DIM;
    return *(const float4*)(p + lane * 4);
}

/* ---------------- merged inits: res rows, then A dense rows (+pack) ------- */
__global__ void k_inits(const int* __restrict__ ini, const int* __restrict__ cnt,
                        const float* __restrict__ deg, float2* __restrict__ pack,
                        const float* __restrict__ du, const float* __restrict__ di,
                        const float* __restrict__ au, const float* __restrict__ ai,
                        const int* __restrict__ uid, const int* __restrict__ iid,
                        float* __restrict__ A, float4* __restrict__ res) {
    const size_t nd8 = (size_t)NDOM * 8;
    const size_t fixed = 2 * nd8;
    size_t work = fixed + (size_t)__ldg(&cnt[2 * CPAD]) * 8;
    size_t stride = (size_t)gridDim.x * blockDim.x;
    for (size_t i = (size_t)blockIdx.x * blockDim.x + threadIdx.x; i < work; i += stride) {
        if (i < nd8) {
            int r = (int)(i >> 3), c = (int)(i & 7);
            float4 v = gatherX(du, di, NDU, r, c);
            res[i] = make_float4(ALPHA * v.x, ALPHA * v.y, ALPHA * v.z, ALPHA * v.w);
        } else if (i < fixed) {
            size_t j = i - nd8;
            int r = (int)(j >> 3), c = (int)(j & 7);
            int node = (r < NDU) ? __ldg(uid + r) : NTU + __ldg(iid + r - NDU);
            float4 v = gatherX(au, ai, NTU, node, c);
            float k = 3.0f * ALPHA;
            res[i] = make_float4(k * v.x, k * v.y, k * v.z, k * v.w);
        } else {
            size_t j = i - fixed;
            int r = (int)(j >> 3), lane = (int)(j & 7);
            int node = __ldg(ini + r);
            int set = node / NALL;
            int so = node - set * NALL;
            if (lane == 0)
                pack[node] = make_float2(nrm(__ldg(deg + node)), __int_as_float(r));
            float4 v = (set == 0) ? gatherX(du, di, NDU, so, lane)
                                  : gatherX(au, ai, NTU, so, lane);
            *(float4*)(A + (size_t)r * DIM + lane * 4) =
                make_float4(ALPHA * v.x, ALPHA * v.y, ALPHA * v.z, ALPHA * v.w);
        }
    }
}

/* ---------------- fused layer-1: 2 edges/lane filter + warp-compacted scatter */
__device__ __forceinline__ void l1_process(unsigned m, int scode, int drow, float w,
                                           unsigned lane,
                                           const float* __restrict__ du,
                                           const float* __restrict__ di,
                                           const float* __restrict__ au,
                                           const float* __restrict__ ai,
                                           float* __restrict__ A) {
    int nv = __popc(m);
    for (int k = 0; k < nv; k += 4) {
        int j = k + (int)(lane >> 3);
        unsigned sl = __fns(m, 0, j + 1);
        int   sc = __shfl_sync(0xffffffffu, scode, sl & 31);
        int   dr = __shfl_sync(0xffffffffu, drow,  sl & 31);
        float ww = __shfl_sync(0xffffffffu, w,     sl & 31);
        if (j < nv) {
            int so = sc & 0x3FFFFFFF;
            int sub = (int)(lane & 7);
            float4 v = (sc >> 30) ? gatherX(au, ai, NTU, so, sub)
                                  : gatherX(du, di, NDU, so, sub);
            float* o = A + (size_t)dr * DIM + sub * 4;
            asm volatile("red.global.add.v4.f32 [%0], {%1,%2,%3,%4};"
                         :: "l"(o), "f"(v.x * ww), "f"(v.y * ww),
                            "f"(v.z * ww), "f"(v.w * ww) : "memory");
        }
    }
}
__global__ void k_scatL1f(const int* __restrict__ dom, const int* __restrict__ sep,
                          const float* __restrict__ deg, const unsigned* __restrict__ needA,
                          const float2* __restrict__ pack,
                          const float* __restrict__ du, const float* __restrict__ di,
                          const float* __restrict__ au, const float* __restrict__ ai,
                          float* __restrict__ A) {
    const unsigned total = 4u * NE;
    unsigned lane = threadIdx.x & 31;
    unsigned warpStride = (gridDim.x * blockDim.x) >> 5;
    unsigned warpId = ((blockIdx.x * blockDim.x) >> 5) + (threadIdx.x >> 5);
    for (unsigned base = warpId * 64; base < total; base += warpStride * 64) {
        unsigned t = base + lane * 2;
        int set = (int)(t / NE);                 /* uniform: NE%64==0 */
        int e   = (int)(t - (unsigned)set * NE);
        const int* dp = dst_ptr(set, dom, sep);
        int2 dd = __ldg((const int2*)(dp + e));
        int idxA = set * NALL + dd.x;
        int idxB = set * NALL + dd.y;
        bool vA = bit_test(needA, idxA);
        bool vB = bit_test(needA, idxB);
        float wA = 0.f, wB = 0.f;
        int drA = 0, drB = 0, scA = 0, scB = 0;
        if (vA | vB) {
            const int* sp = src_ptr(set, dom, sep);
            int2 ss = __ldg((const int2*)(sp + e));
            const float* dg = deg + (size_t)set * NALL;
            int tb = (set > 0) << 30;
            if (vA) {
                float2 pk = __ldg(pack + idxA);
                wA = BETA * nrm(__ldg(dg + ss.x)) * pk.x;
                drA = __float_as_int(pk.y);
                scA = ss.x | tb;
            }
            if (vB) {
                float2 pk = __ldg(pack + idxB);
                wB = BETA * nrm(__ldg(dg + ss.y)) * pk.x;
                drB = __float_as_int(pk.y);
                scB = ss.y | tb;
            }
        }
        unsigned mA = __ballot_sync(0xffffffffu, vA);
        unsigned mB = __ballot_sync(0xffffffffu, vB);
        if (mA) l1_process(mA, scA, drA, wA, lane, du, di, au, ai, A);
        if (mB) l1_process(mB, scB, drB, wB, lane, du, di, au, ai, A);
    }
}

/* ---------------- layer-2 scatter with fused resolve: 4 edges per warp ---- */
__global__ void k_scatL2(const int* __restrict__ l2s, const int* __restrict__ l2d,
                         const int* __restrict__ l2r, const int* __restrict__ cnt,
                         const float* __restrict__ deg, const float2* __restrict__ pack,
                         const float* __restrict__ A, float* __restrict__ res) {
    int n = __ldg(&cnt[0]);
    unsigned lane = threadIdx.x & 31;
    unsigned warpStride = (gridDim.x * blockDim.x) >> 5;
    unsigned warpId = ((blockIdx.x * blockDim.x) >> 5) + (threadIdx.x >> 5);
    int j = (int)(lane >> 3), sub = (int)(lane & 7);
    for (int eb = (int)warpId * 4; eb < n; eb += (int)warpStride * 4) {
        int e = eb + j;
        float w = 0.f;
        int drow = 0, rrow = 0;
        if (sub == 0 && e < n) {
            int srow = __ldg(l2s + e);
            int set = srow / NALL;
            float2 pk = __ldg(pack + srow);
            w = BETA * pk.x * nrm(__ldg(deg + (size_t)set * NALL + __ldg(l2d + e)));
            drow = __float_as_int(pk.y);
            rrow = __ldg(l2r + e);
        }
        unsigned lead = lane & ~7u;
        w    = __shfl_sync(0xffffffffu, w,    lead);
        drow = __shfl_sync(0xffffffffu, drow, lead);
        rrow = __shfl_sync(0xffffffffu, rrow, lead);
        if (e < n) {
            float4 v = *(const float4*)(A + (size_t)drow * DIM + sub * 4);
            float* o = res + (size_t)rrow * DIM + sub * 4;
            asm volatile("red.global.add.v4.f32 [%0], {%1,%2,%3,%4};"
                         :: "l"(o), "f"(v.x * w), "f"(v.y * w),
                            "f"(v.z * w), "f"(v.w * w) : "memory");
        }
    }
}

/* gamma[p] = dot(light_u, light_i)/9 + dot(intra_u, intra_i); one warp/pair */
__global__ void k_gamma(const void* __restrict__ users, const void* __restrict__ items,
                        const float* __restrict__ res, float* __restrict__ out) {
    int p = (blockIdx.x * blockDim.x + threadIdx.x) >> 5;
    int lane = threadIdx.x & 31;
    if (p >= NQ) return;
    long long u  = g_f[0] ? ((const long long*)users)[p] : (long long)((const int*)users)[p];
    long long it = g_f[1] ? ((const long long*)items)[p] : (long long)((const int*)items)[p];
    size_t ui = (size_t)u * DIM + lane;
    size_t ii = ((size_t)NDU + it) * DIM + lane;
    size_t ul = ((size_t)NDOM + u) * DIM + lane;
    size_t il = ((size_t)NDOM + NDU + it) * DIM + lane;
    float v = res[ul] * res[il] * (1.0f / 9.0f) + res[ui] * res[ii];
#pragma unroll
    for (int o = 16; o; o >>= 1) v += __shfl_xor_sync(0xffffffffu, v, o);
    if (lane == 0) out[p] = v;
}

/* ---------------- host side ---------------- */
static inline unsigned gb(size_t n) { return (unsigned)((n + 255) / 256); }

extern "C" void kernel_launch(void* const* d_in, const int* in_sizes, int n_in,
                              void* d_out, int out_size) {
    const int*   dom   = (const int*)d_in[0];
    const int*   sep   = (const int*)d_in[1];
    const float* aggru = (const float*)d_in[2];
    const float* aggri = (const float*)d_in[3];
    const float* domu  = (const float*)d_in[4];
    const float* domi  = (const float*)d_in[5];
    const int*   uid   = (const int*)d_in[6];
    const int*   iid   = (const int*)d_in[7];
    const void*  users = d_in[8];
    const void*  items = d_in[9];
    float* out = (float*)d_out;

    float *A, *res, *deg;
    float2* pack;
    int *l2s, *l2d, *l2r, *ini, *remap, *cnt;
    unsigned *needA, *bitL, *bitG;
    cudaGetSymbolAddress((void**)&A, g_A);
    cudaGetSymbolAddress((void**)&res, g_res);
    cudaGetSymbolAddress((void**)&deg, g_deg);
    cudaGetSymbolAddress((void**)&pack, g_pack);
    cudaGetSymbolAddress((void**)&l2s, g_l2s);
    cudaGetSymbolAddress((void**)&l2d, g_l2d);
    cudaGetSymbolAddress((void**)&l2r, g_l2r);
    cudaGetSymbolAddress((void**)&ini, g_ini);
    cudaGetSymbolAddress((void**)&needA, g_needA);
    cudaGetSymbolAddress((void**)&bitL, g_bitL);
    cudaGetSymbolAddress((void**)&bitG, g_bitG);
    cudaGetSymbolAddress((void**)&remap, g_remap);
    cudaGetSymbolAddress((void**)&cnt, g_cnt);

    /* setup */
    k_detect<<<64, 256>>>((const int*)users, (const int*)items);
    k_clear<<<gb(500000), 256>>>((float4*)deg, (uint4*)needA,
                                 (uint4*)bitL, (uint4*)bitG, cnt);
    k_needmap<<<gb(NQ), 256>>>(bitL, bitG, remap, uid, iid, users, items);

    /* degree + layer-2 compaction (4 edges/thread), then needA -> ini */
    unsigned degGrid = (unsigned)(((size_t)4 * QNE + DBLK - 1) / DBLK);
    k_degA<<<degGrid, DBLK>>>(dom, sep, deg, bitL, bitG, remap, needA, cnt,
                              l2s, l2d, l2r);
    k_build<<<(NBITW + 255) / 256, 256>>>(needA, ini, cnt);

    /* merged inits (res + A + pack) + layer-1 fused scatter */
    k_inits<<<2048, 256>>>(ini, cnt, deg, pack, domu, domi, aggru, aggri,
                           uid, iid, A, (float4*)res);
    k_scatL1f<<<2048, 256>>>(dom, sep, deg, needA, pack,
                             domu, domi, aggru, aggri, A);

    /* layer-2 scatter (resolve fused) */
    k_scatL2<<<1024, 256>>>(l2s, l2d, l2r, cnt, deg, pack, A, res);

    /* final dots */
    k_gamma<<<NQ / 8, 256>>>(users, items, res, out);
}

// round 16
// speedup vs baseline: 1.1559x; 1.0507x over previous
#include <cuda_runtime.h>
#include <stdint.h>

#define NDU 60000
#define NDI 90000
#define NDOM (NDU + NDI)      /* 150000 */
#define NTU 200000
#define NTI 300000
#define NALL (NTU + NTI)      /* 500000 */
#define NE  2000000
#define DIM 32
#define NQ  8192
#define ALPHA 0.1f
#define BETA  0.9f
#define CPAD 256
#define NBITW ((4 * NALL) / 32)   /* 62500 */
#define NBL   4704
#define NBG   15628
#define DBLK 512
#define QNE  500000               /* NE/4: threads per set in degA */

/* ---------------- static device scratch (no allocs allowed) ---------------- */
__device__ __align__(16) float g_A[(size_t)4 * NALL * DIM];
__device__ __align__(16) float g_res[(size_t)2 * NDOM * DIM]; /* intra | light */
__device__ __align__(16) float    g_deg[4 * (size_t)NALL];
__device__ __align__(16) float2   g_pack[4 * (size_t)NALL];  /* (nrm, denseRow) */
__device__ __align__(16) int      g_l2s[4 * (size_t)NE];
__device__ __align__(16) int      g_l2d[4 * (size_t)NE];
__device__ __align__(16) int      g_l2r[4 * (size_t)NE];
__device__ __align__(16) int      g_ini[4 * (size_t)NALL];
__device__ __align__(16) unsigned g_needA[NBITW];
__device__ __align__(16) unsigned g_bitL[NBL];
__device__ __align__(16) unsigned g_bitG[NBG];
__device__ __align__(16) int      g_remap[NALL];
__device__ int      g_cnt[3 * CPAD];
__device__ int      g_f[2] = {1, 1};

/* ---------------- edge-list addressing ---------------- */
__device__ __forceinline__ const int* src_ptr(int set, const int* dom, const int* sep) {
    return (set == 0) ? dom : sep + (size_t)(set - 1) * 2 * NE;
}
__device__ __forceinline__ const int* dst_ptr(int set, const int* dom, const int* sep) {
    return (set == 0) ? dom + NE : sep + (size_t)(set - 1) * 2 * NE + NE;
}

__device__ __forceinline__ float nrm(float deg) { return rsqrtf(fmaxf(deg, 1.0f)); }
__device__ __forceinline__ bool bit_test(const unsigned* __restrict__ b, int i) {
    return (__ldg(b + (i >> 5)) >> (i & 31)) & 1u;
}
__device__ __forceinline__ long long qidx(const void* p, int flag, int i) {
    return flag ? ((const long long*)p)[i] : (long long)((const int*)p)[i];
}

/* ---------------- setup: clear + width-detect fused ---------------- */
__global__ void k_cleardet(float4* __restrict__ deg4, uint4* __restrict__ needA4,
                           uint4* __restrict__ bitL4, uint4* __restrict__ bitG4,
                           int* __restrict__ cnt,
                           const int* __restrict__ ua, const int* __restrict__ ib) {
    int i = blockIdx.x * blockDim.x + threadIdx.x;
    if (i < 500000) deg4[i] = make_float4(0.f, 0.f, 0.f, 0.f);
    if (i < 15625)  needA4[i] = make_uint4(0u, 0u, 0u, 0u);
    if (i < NBL / 4) bitL4[i] = make_uint4(0u, 0u, 0u, 0u);
    if (i < NBG / 4) bitG4[i] = make_uint4(0u, 0u, 0u, 0u);
    if (i < 3 * CPAD) cnt[i] = 0;
    /* monotone width detect: only writes 0; int32 re-flips on every call */
    if (i < NQ) {
        if (ua[2 * i + 1] != 0) g_f[0] = 0;
        if (ib[2 * i + 1] != 0) g_f[1] = 0;
    }
}
__global__ void k_needmap(unsigned* __restrict__ bitL, unsigned* __restrict__ bitG,
                          int* __restrict__ remap,
                          const int* __restrict__ uid, const int* __restrict__ iid,
                          const void* __restrict__ users, const void* __restrict__ items) {
    int i = blockIdx.x * blockDim.x + threadIdx.x;
    if (i >= NQ) return;
    long long u  = qidx(users, g_f[0], i);
    long long it = qidx(items, g_f[1], i);
    int r1 = (int)u, r2 = NDU + (int)it;
    atomicOr(&bitL[r1 >> 5], 1u << (r1 & 31));
    atomicOr(&bitL[r2 >> 5], 1u << (r2 & 31));
    int n1 = __ldg(uid + u), n2 = NTU + __ldg(iid + it);
    atomicOr(&bitG[n1 >> 5], 1u << (n1 & 31));
    atomicOr(&bitG[n2 >> 5], 1u << (n2 & 31));
    remap[n1] = r1;
    remap[n2] = r2;
}

/* ---------------- degA: 4 edges/thread (int4); deg histogram + L2 compaction
   + needA marking. One counter atomic per block.                            */
__global__ __launch_bounds__(DBLK) void
k_degA(const int* __restrict__ dom, const int* __restrict__ sep,
       float* __restrict__ deg, const unsigned* __restrict__ bitL,
       const unsigned* __restrict__ bitG, const int* __restrict__ remap,
       unsigned* __restrict__ needA, int* __restrict__ cnt,
       int* __restrict__ l2s, int* __restrict__ l2d, int* __restrict__ l2r) {
    __shared__ int w2[DBLK / 32];
    __shared__ int base2;
    size_t t = (size_t)blockIdx.x * DBLK + threadIdx.x;
    bool in = t < (size_t)4 * QNE;
    size_t tt = in ? t : 0;
    int lane = threadIdx.x & 31, wid = threadIdx.x >> 5;
    int set = (int)(tt / QNE);                  /* uniform per warp: QNE%32==0 */
    int e   = (int)(tt - (size_t)set * QNE) * 4;
    const int* dp = dst_ptr(set, dom, sep);
    int4 dd = __ldg((const int4*)(dp + e));
    float* dg = deg + (size_t)set * NALL;
    if (in) {
        atomicAdd(dg + dd.x, 1.0f);
        atomicAdd(dg + dd.y, 1.0f);
        atomicAdd(dg + dd.z, 1.0f);
        atomicAdd(dg + dd.w, 1.0f);
    }
    bool vA = false, vB = false, vC = false, vD = false;
    int rA = 0, rB = 0, rC = 0, rD = 0;
    if (in) {
        if (set == 0) {
            vA = bit_test(bitL, dd.x); rA = dd.x;
            vB = bit_test(bitL, dd.y); rB = dd.y;
            vC = bit_test(bitL, dd.z); rC = dd.z;
            vD = bit_test(bitL, dd.w); rD = dd.w;
        } else {
            vA = bit_test(bitG, dd.x);
            vB = bit_test(bitG, dd.y);
            vC = bit_test(bitG, dd.z);
            vD = bit_test(bitG, dd.w);
            if (vA) rA = NDOM + __ldg(remap + dd.x);
            if (vB) rB = NDOM + __ldg(remap + dd.y);
            if (vC) rC = NDOM + __ldg(remap + dd.z);
            if (vD) rD = NDOM + __ldg(remap + dd.w);
        }
    }
    int iA = 0, iB = 0, iC = 0, iD = 0;
    if (vA | vB | vC | vD) {
        const int* sp = src_ptr(set, dom, sep);
        int4 ss = __ldg((const int4*)(sp + e));
        iA = set * NALL + ss.x; iB = set * NALL + ss.y;
        iC = set * NALL + ss.z; iD = set * NALL + ss.w;
        if (vA) atomicOr(&needA[iA >> 5], 1u << (iA & 31));
        if (vB) atomicOr(&needA[iB >> 5], 1u << (iB & 31));
        if (vC) atomicOr(&needA[iC >> 5], 1u << (iC & 31));
        if (vD) atomicOr(&needA[iD >> 5], 1u << (iD & 31));
    }
    unsigned mA = __ballot_sync(0xffffffffu, vA);
    unsigned mB = __ballot_sync(0xffffffffu, vB);
    unsigned mC = __ballot_sync(0xffffffffu, vC);
    unsigned mD = __ballot_sync(0xffffffffu, vD);
    if (lane == 0) w2[wid] = __popc(mA) + __popc(mB) + __popc(mC) + __popc(mD);
    __syncthreads();
    if (threadIdx.x == 0) {
        int tot = 0;
#pragma unroll
        for (int i = 0; i < DBLK / 32; i++) { int c = w2[i]; w2[i] = tot; tot += c; }
        base2 = tot ? atomicAdd(&cnt[0], tot) : 0;
    }
    __syncthreads();
    unsigned ltm = (1u << lane) - 1u;
    int wb = base2 + w2[wid];
    int cA = __popc(mA), cB = __popc(mB), cC = __popc(mC);
    if (vA) { int p = wb + __popc(mA & ltm);                 l2s[p] = iA; l2d[p] = dd.x; l2r[p] = rA; }
    if (vB) { int p = wb + cA + __popc(mB & ltm);            l2s[p] = iB; l2d[p] = dd.y; l2r[p] = rB; }
    if (vC) { int p = wb + cA + cB + __popc(mC & ltm);       l2s[p] = iC; l2d[p] = dd.z; l2r[p] = rC; }
    if (vD) { int p = wb + cA + cB + cC + __popc(mD & ltm);  l2s[p] = iD; l2d[p] = dd.w; l2r[p] = rD; }
}

/* ---------------- build ini list from needA bitmask (pure bit-scan) ------- */
__global__ void k_build(const unsigned* __restrict__ needA,
                        int* __restrict__ ini, int* __restrict__ cnt) {
    __shared__ int wtot[8];
    __shared__ int sBase;
    int w = blockIdx.x * 256 + threadIdx.x;
    int lane = threadIdx.x & 31, wid = threadIdx.x >> 5;
    unsigned word = (w < NBITW) ? needA[w] : 0u;
    int c = __popc(word);
    int x = c;
#pragma unroll
    for (int off = 1; off < 32; off <<= 1) {
        int y = __shfl_up_sync(0xffffffffu, x, off);
        if (lane >= off) x += y;
    }
    if (lane == 31) wtot[wid] = x;
    __syncthreads();
    if (threadIdx.x == 0) {
        int tot = 0;
#pragma unroll
        for (int i = 0; i < 8; i++) { int t = wtot[i]; wtot[i] = tot; tot += t; }
        sBase = tot ? atomicAdd(&cnt[2 * CPAD], tot) : 0;
    }
    __syncthreads();
    int off0 = sBase + wtot[wid] + (x - c);
    int k = 0;
    while (word) {
        int b = __ffs(word) - 1;
        word &= word - 1;
        ini[off0 + k++] = w * 32 + b;
    }
}

/* ---------------- gathers from split input tables ---------------- */
__device__ __forceinline__ float4 gatherX(const float* __restrict__ xu,
                                          const float* __restrict__ xi,
                                          int splitU, int node, int lane) {
    const float* p = (node < splitU) ? xu + (size_t)node * DIM
                                     : xi + (size_t)(node - splitU) * DIM;
    return *(const float4*)(p + lane * 4);
}

/* ---------------- inits: query-driven res rows + dense A rows (+pack) ----- */
__global__ void k_inits(const int* __restrict__ ini, const int* __restrict__ cnt,
                        const float* __restrict__ deg, float2* __restrict__ pack,
                        const float* __restrict__ du, const float* __restrict__ di,
                        const float* __restrict__ au, const float* __restrict__ ai,
                        const int* __restrict__ uid, const int* __restrict__ iid,
                        const void* __restrict__ users, const void* __restrict__ items,
                        float* __restrict__ A, float* __restrict__ res) {
    const size_t seg = (size_t)NQ * 8;
    const size_t fixed = 4 * seg;
    size_t work = fixed + (size_t)__ldg(&cnt[2 * CPAD]) * 8;
    size_t stride = (size_t)gridDim.x * blockDim.x;
    int f0 = g_f[0], f1 = g_f[1];
    for (size_t i = (size_t)blockIdx.x * blockDim.x + threadIdx.x; i < work; i += stride) {
        if (i < fixed) {
            int sg = (int)(i / seg);
            int j  = (int)(i - (size_t)sg * seg);
            int q = j >> 3, c = j & 7;
            size_t row;
            float4 v;
            float k;
            if (sg == 0) {        /* intra user */
                long long u = qidx(users, f0, q);
                row = (size_t)u;
                v = *(const float4*)(du + u * DIM + c * 4);
                k = ALPHA;
            } else if (sg == 1) { /* intra item */
                long long it = qidx(items, f1, q);
                row = (size_t)NDU + it;
                v = *(const float4*)(di + it * DIM + c * 4);
                k = ALPHA;
            } else if (sg == 2) { /* light user */
                long long u = qidx(users, f0, q);
                row = (size_t)NDOM + u;
                v = *(const float4*)(au + (size_t)__ldg(uid + u) * DIM + c * 4);
                k = 3.0f * ALPHA;
            } else {              /* light item */
                long long it = qidx(items, f1, q);
                row = (size_t)NDOM + NDU + it;
                v = *(const float4*)(ai + (size_t)__ldg(iid + it) * DIM + c * 4);
                k = 3.0f * ALPHA;
            }
            *(float4*)(res + row * DIM + c * 4) =
                make_float4(k * v.x, k * v.y, k * v.z, k * v.w);
        } else {
            size_t j = i - fixed;
            int r = (int)(j >> 3), lane = (int)(j & 7);
            int node = __ldg(ini + r);
            int set = node / NALL;
            int so = node - set * NALL;
            if (lane == 0)
                pack[node] = make_float2(nrm(__ldg(deg + node)), __int_as_float(r));
            float4 v = (set == 0) ? gatherX(du, di, NDU, so, lane)
                                  : gatherX(au, ai, NTU, so, lane);
            *(float4*)(A + (size_t)r * DIM + lane * 4) =
                make_float4(ALPHA * v.x, ALPHA * v.y, ALPHA * v.z, ALPHA * v.w);
        }
    }
}

/* ---------------- fused layer-1: 2 edges/lane filter + warp-compacted scatter */
__device__ __forceinline__ void l1_process(unsigned m, int scode, int drow, float w,
                                           unsigned lane,
                                           const float* __restrict__ du,
                                           const float* __restrict__ di,
                                           const float* __restrict__ au,
                                           const float* __restrict__ ai,
                                           float* __restrict__ A) {
    int nv = __popc(m);
    for (int k = 0; k < nv; k += 4) {
        int j = k + (int)(lane >> 3);
        unsigned sl = __fns(m, 0, j + 1);
        int   sc = __shfl_sync(0xffffffffu, scode, sl & 31);
        int   dr = __shfl_sync(0xffffffffu, drow,  sl & 31);
        float ww = __shfl_sync(0xffffffffu, w,     sl & 31);
        if (j < nv) {
            int so = sc & 0x3FFFFFFF;
            int sub = (int)(lane & 7);
            float4 v = (sc >> 30) ? gatherX(au, ai, NTU, so, sub)
                                  : gatherX(du, di, NDU, so, sub);
            float* o = A + (size_t)dr * DIM + sub * 4;
            asm volatile("red.global.add.v4.f32 [%0], {%1,%2,%3,%4};"
                         :: "l"(o), "f"(v.x * ww), "f"(v.y * ww),
                            "f"(v.z * ww), "f"(v.w * ww) : "memory");
        }
    }
}
__global__ void k_scatL1f(const int* __restrict__ dom, const int* __restrict__ sep,
                          const float* __restrict__ deg, const unsigned* __restrict__ needA,
                          const float2* __restrict__ pack,
                          const float* __restrict__ du, const float* __restrict__ di,
                          const float* __restrict__ au, const float* __restrict__ ai,
                          float* __restrict__ A) {
    const unsigned total = 4u * NE;
    unsigned lane = threadIdx.x & 31;
    unsigned warpStride = (gridDim.x * blockDim.x) >> 5;
    unsigned warpId = ((blockIdx.x * blockDim.x) >> 5) + (threadIdx.x >> 5);
    for (unsigned base = warpId * 64; base < total; base += warpStride * 64) {
        unsigned t = base + lane * 2;
        int set = (int)(t / NE);                 /* uniform: NE%64==0 */
        int e   = (int)(t - (unsigned)set * NE);
        const int* dp = dst_ptr(set, dom, sep);
        int2 dd = __ldg((const int2*)(dp + e));
        int idxA = set * NALL + dd.x;
        int idxB = set * NALL + dd.y;
        bool vA = bit_test(needA, idxA);
        bool vB = bit_test(needA, idxB);
        float wA = 0.f, wB = 0.f;
        int drA = 0, drB = 0, scA = 0, scB = 0;
        if (vA | vB) {
            const int* sp = src_ptr(set, dom, sep);
            int2 ss = __ldg((const int2*)(sp + e));
            const float* dg = deg + (size_t)set * NALL;
            int tb = (set > 0) << 30;
            if (vA) {
                float2 pk = __ldg(pack + idxA);
                wA = BETA * nrm(__ldg(dg + ss.x)) * pk.x;
                drA = __float_as_int(pk.y);
                scA = ss.x | tb;
            }
            if (vB) {
                float2 pk = __ldg(pack + idxB);
                wB = BETA * nrm(__ldg(dg + ss.y)) * pk.x;
                drB = __float_as_int(pk.y);
                scB = ss.y | tb;
            }
        }
        unsigned mA = __ballot_sync(0xffffffffu, vA);
        unsigned mB = __ballot_sync(0xffffffffu, vB);
        if (mA) l1_process(mA, scA, drA, wA, lane, du, di, au, ai, A);
        if (mB) l1_process(mB, scB, drB, wB, lane, du, di, au, ai, A);
    }
}

/* ---------------- layer-2 scatter with fused resolve: 4 edges per warp ---- */
__global__ void k_scatL2(const int* __restrict__ l2s, const int* __restrict__ l2d,
                         const int* __restrict__ l2r, const int* __restrict__ cnt,
                         const float* __restrict__ deg, const float2* __restrict__ pack,
                         const float* __restrict__ A, float* __restrict__ res) {
    int n = __ldg(&cnt[0]);
    unsigned lane = threadIdx.x & 31;
    unsigned warpStride = (gridDim.x * blockDim.x) >> 5;
    unsigned warpId = ((blockIdx.x * blockDim.x) >> 5) + (threadIdx.x >> 5);
    int j = (int)(lane >> 3), sub = (int)(lane & 7);
    for (int eb = (int)warpId * 4; eb < n; eb += (int)warpStride * 4) {
        int e = eb + j;
        float w = 0.f;
        int drow = 0, rrow = 0;
        if (sub == 0 && e < n) {
            int srow = __ldg(l2s + e);
            int set = srow / NALL;
            float2 pk = __ldg(pack + srow);
            w = BETA * pk.x * nrm(__ldg(deg + (size_t)set * NALL + __ldg(l2d + e)));
            drow = __float_as_int(pk.y);
            rrow = __ldg(l2r + e);
        }
        unsigned lead = lane & ~7u;
        w    = __shfl_sync(0xffffffffu, w,    lead);
        drow = __shfl_sync(0xffffffffu, drow, lead);
        rrow = __shfl_sync(0xffffffffu, rrow, lead);
        if (e < n) {
            float4 v = *(const float4*)(A + (size_t)drow * DIM + sub * 4);
            float* o = res + (size_t)rrow * DIM + sub * 4;
            asm volatile("red.global.add.v4.f32 [%0], {%1,%2,%3,%4};"
                         :: "l"(o), "f"(v.x * w), "f"(v.y * w),
                            "f"(v.z * w), "f"(v.w * w) : "memory");
        }
    }
}

/* gamma[p] = dot(light_u, light_i)/9 + dot(intra_u, intra_i); one warp/pair */
__global__ void k_gamma(const void* __restrict__ users, const void* __restrict__ items,
                        const float* __restrict__ res, float* __restrict__ out) {
    int p = (blockIdx.x * blockDim.x + threadIdx.x) >> 5;
    int lane = threadIdx.x & 31;
    if (p >= NQ) return;
    long long u  = qidx(users, g_f[0], p);
    long long it = qidx(items, g_f[1], p);
    size_t ui = (size_t)u * DIM + lane;
    size_t ii = ((size_t)NDU + it) * DIM + lane;
    size_t ul = ((size_t)NDOM + u) * DIM + lane;
    size_t il = ((size_t)NDOM + NDU + it) * DIM + lane;
    float v = res[ul] * res[il] * (1.0f / 9.0f) + res[ui] * res[ii];
#pragma unroll
    for (int o = 16; o; o >>= 1) v += __shfl_xor_sync(0xffffffffu, v, o);
    if (lane == 0) out[p] = v;
}

/* ---------------- host side ---------------- */
static inline unsigned gb(size_t n) { return (unsigned)((n + 255) / 256); }

extern "C" void kernel_launch(void* const* d_in, const int* in_sizes, int n_in,
                              void* d_out, int out_size) {
    const int*   dom   = (const int*)d_in[0];
    const int*   sep   = (const int*)d_in[1];
    const float* aggru = (const float*)d_in[2];
    const float* aggri = (const float*)d_in[3];
    const float* domu  = (const float*)d_in[4];
    const float* domi  = (const float*)d_in[5];
    const int*   uid   = (const int*)d_in[6];
    const int*   iid   = (const int*)d_in[7];
    const void*  users = d_in[8];
    const void*  items = d_in[9];
    float* out = (float*)d_out;

    float *A, *res, *deg;
    float2* pack;
    int *l2s, *l2d, *l2r, *ini, *remap, *cnt;
    unsigned *needA, *bitL, *bitG;
    cudaGetSymbolAddress((void**)&A, g_A);
    cudaGetSymbolAddress((void**)&res, g_res);
    cudaGetSymbolAddress((void**)&deg, g_deg);
    cudaGetSymbolAddress((void**)&pack, g_pack);
    cudaGetSymbolAddress((void**)&l2s, g_l2s);
    cudaGetSymbolAddress((void**)&l2d, g_l2d);
    cudaGetSymbolAddress((void**)&l2r, g_l2r);
    cudaGetSymbolAddress((void**)&ini, g_ini);
    cudaGetSymbolAddress((void**)&needA, g_needA);
    cudaGetSymbolAddress((void**)&bitL, g_bitL);
    cudaGetSymbolAddress((void**)&bitG, g_bitG);
    cudaGetSymbolAddress((void**)&remap, g_remap);
    cudaGetSymbolAddress((void**)&cnt, g_cnt);

    /* setup (clear + width-detect fused) */
    k_cleardet<<<gb(500000), 256>>>((float4*)deg, (uint4*)needA,
                                    (uint4*)bitL, (uint4*)bitG, cnt,
                                    (const int*)users, (const int*)items);
    k_needmap<<<gb(NQ), 256>>>(bitL, bitG, remap, uid, iid, users, items);

    /* degree + layer-2 compaction (4 edges/thread), then needA -> ini */
    unsigned degGrid = (unsigned)(((size_t)4 * QNE + DBLK - 1) / DBLK);
    k_degA<<<degGrid, DBLK>>>(dom, sep, deg, bitL, bitG, remap, needA, cnt,
                              l2s, l2d, l2r);
    k_build<<<(NBITW + 255) / 256, 256>>>(needA, ini, cnt);

    /* query-driven inits (res + A + pack) + layer-1 fused scatter */
    k_inits<<<2048, 256>>>(ini, cnt, deg, pack, domu, domi, aggru, aggri,
                           uid, iid, users, items, A, res);
    k_scatL1f<<<2048, 256>>>(dom, sep, deg, needA, pack,
                             domu, domi, aggru, aggri, A);

    /* layer-2 scatter (resolve fused) */
    k_scatL2<<<1024, 256>>>(l2s, l2d, l2r, cnt, deg, pack, A, res);

    /* final dots */
    k_gamma<<<NQ / 8, 256>>>(users, items, res, out);
}